// round 2
// baseline (speedup 1.0000x reference)
#include <cuda_runtime.h>
#include <math.h>

#define NB 4
#define NE 100000
#define NT 100000
#define ND 64
#define HSZ 1024
#define HSZ2 2048
#define MAX1 4096
#define MAX2 16384
#define MAXSUP 1024
#define EPSV 1e-6f

// scratch state (device globals; re-initialized every launch by k_init)
__device__ int   g_s0[NB];
__device__ int   g_cnt1, g_cnt2, g_nsup;
__device__ int   g_list1[MAX1];
__device__ int   g_list2[MAX2];
__device__ int   g_sup[MAXSUP];        // packed: e | (b << 17)   (e < 2^17)
__device__ int   g_hkey[HSZ];
__device__ float g_hep[HSZ];
__device__ float g_hhist[HSZ][ND];
__device__ int   g_h2key[HSZ2];
__device__ float g_h2ep[HSZ2];

__device__ __forceinline__ float sigm(float x) { return 1.0f / (1.0f + expf(-x)); }

__device__ __forceinline__ int hinsert1(int key, int* isnew) {
    unsigned h = ((unsigned)key * 2654435761u) & (HSZ - 1);
    for (int p = 0; p < HSZ; p++) {
        int prev = atomicCAS(&g_hkey[h], -1, key);
        if (prev == -1) { *isnew = 1; return (int)h; }
        if (prev == key) { *isnew = 0; return (int)h; }
        h = (h + 1) & (HSZ - 1);
    }
    *isnew = 0;
    return -1;
}

__device__ __forceinline__ int hfind1(int key) {
    unsigned h = ((unsigned)key * 2654435761u) & (HSZ - 1);
    for (int p = 0; p < HSZ; p++) {
        int k = g_hkey[h];
        if (k == key) return (int)h;
        if (k == -1) return -1;
        h = (h + 1) & (HSZ - 1);
    }
    return -1;
}

__device__ __forceinline__ int hinsert2(int key) {
    unsigned h = ((unsigned)key * 2654435761u) & (HSZ2 - 1);
    for (int p = 0; p < HSZ2; p++) {
        int prev = atomicCAS(&g_h2key[h], -1, key);
        if (prev == -1 || prev == key) return (int)h;
        h = (h + 1) & (HSZ2 - 1);
    }
    return -1;
}

// K1: zero output (float4), find one-hot start entity per batch (float4 scan),
//     clear hashes and counters. NE % 4 == 0, so each float4 is within one batch.
__global__ void k_init(const float4* __restrict__ start4, float4* __restrict__ out4)
{
    int idx = blockIdx.x * blockDim.x + threadIdx.x;   // 0 .. NB*NE/4-1
    if (idx < (NB * NE) / 4) {
        out4[idx] = make_float4(0.f, 0.f, 0.f, 0.f);
        float4 s = start4[idx];
        if (s.x != 0.f || s.y != 0.f || s.z != 0.f || s.w != 0.f) {
            int b  = idx / (NE / 4);
            int p0 = idx * 4 - b * NE;
            if (s.x != 0.f) g_s0[b] = p0;
            if (s.y != 0.f) g_s0[b] = p0 + 1;
            if (s.z != 0.f) g_s0[b] = p0 + 2;
            if (s.w != 0.f) g_s0[b] = p0 + 3;
        }
    }
    if (idx < (HSZ * ND) / 4) ((float4*)g_hhist)[idx] = make_float4(0.f, 0.f, 0.f, 0.f);
    if (idx < HSZ)  { g_hkey[idx]  = -1; g_hep[idx]  = 0.f; }
    if (idx < HSZ2) { g_h2key[idx] = -1; g_h2ep[idx] = 0.f; }
    if (idx == 0) { g_cnt1 = 0; g_cnt2 = 0; g_nsup = 0; }
}

// K2: collect triples whose subject equals a batch's start entity (register compare)
__global__ void k_hop1_collect(const int* __restrict__ kb)
{
    int t = blockIdx.x * blockDim.x + threadIdx.x;
    if (t >= NT) return;
    int s = kb[3 * t];
    int a0 = g_s0[0], a1 = g_s0[1], a2 = g_s0[2], a3 = g_s0[3];
    unsigned m = (unsigned)(s == a0) | ((unsigned)(s == a1) << 1)
               | ((unsigned)(s == a2) << 2) | ((unsigned)(s == a3) << 3);
    while (m) {
        int b = __ffs(m) - 1; m &= m - 1;
        int i = atomicAdd(&g_cnt1, 1);
        if (i < MAX1) g_list1[i] = t * 4 + b;
    }
}

// K3: step-0 GRU cell (h = 0) per hop-1 triple; accumulate (ep, hist) into hash1;
//     build compact support list. cq computed inline. One 64-thread block / entry.
__global__ void k_hop1_proc(const int* __restrict__ kb, const float* __restrict__ rel_emb,
                            const float* __restrict__ W_step, const float* __restrict__ b_step,
                            const int* __restrict__ query,
                            const float* __restrict__ w_ih, const float* __restrict__ b_ih,
                            const float* __restrict__ b_hh, const float* __restrict__ w_cls,
                            const float* __restrict__ b_cls)
{
    __shared__ float s_cq[NB][ND];
    __shared__ float s_rf[ND], s_red[ND];
    __shared__ int   s_slot;
    __shared__ float s_objp;
    int d = threadIdx.x;

    #pragma unroll
    for (int b = 0; b < NB; b++) {
        int q = query[b];
        float acc = b_step[d];                       // step 0
        #pragma unroll 8
        for (int i = 0; i < ND; i++)
            acc += rel_emb[q * ND + i] * W_step[i * ND + d];
        s_cq[b][d] = tanhf(acc);
    }
    __syncthreads();

    int n = min(g_cnt1, MAX1);
    for (int i = blockIdx.x; i < n; i += gridDim.x) {
        int code = g_list1[i];
        int t = code >> 2, b = code & 3;
        int e = kb[3 * t + 1], rid = kb[3 * t + 2];

        s_rf[d] = rel_emb[rid * ND + d];
        __syncthreads();

        float xr = b_ih[d], xz = b_ih[ND + d], xn = b_ih[2 * ND + d];
        const float* wr = w_ih + d * ND;
        const float* wz = w_ih + (ND + d) * ND;
        const float* wn = w_ih + (2 * ND + d) * ND;
        #pragma unroll 8
        for (int k = 0; k < ND; k++) {
            float f = s_rf[k];
            xr += f * wr[k]; xz += f * wz[k]; xn += f * wn[k];
        }
        // h = 0 -> h_proj = b_hh
        float r  = sigm(xr + b_hh[d]);
        float z  = sigm(xz + b_hh[ND + d]);
        float nn = tanhf(xn + r * b_hh[2 * ND + d]);
        float trans = (1.0f - z) * nn;               // + z*h with h=0

        s_red[d] = trans * s_cq[b][d] * w_cls[d];
        __syncthreads();
        if (d == 0) {
            float logit = b_cls[0];
            for (int k = 0; k < ND; k++) logit += s_red[k];
            float p = sigm(logit);                   // obj_p = 1.0 * p
            s_objp = p;
            int isnew;
            int slot = hinsert1(b * NE + e, &isnew);
            s_slot = slot;
            if (slot >= 0) {
                if (isnew) {
                    int j = atomicAdd(&g_nsup, 1);
                    if (j < MAXSUP) g_sup[j] = e | (b << 17);
                }
                atomicAdd(&g_hep[slot], p);
            }
        }
        __syncthreads();
        if (s_slot >= 0) atomicAdd(&g_hhist[s_slot][d], trans * s_objp);
        __syncthreads();
    }
}

// K4: collect triples whose subject is in the hop-1 support (smem list compare)
__global__ void k_hop2_collect(const int* __restrict__ kb)
{
    __shared__ int s_sup[MAXSUP];
    __shared__ int s_ns;
    if (threadIdx.x == 0) s_ns = min(g_nsup, MAXSUP);
    __syncthreads();
    int ns = s_ns;
    for (int j = threadIdx.x; j < ns; j += blockDim.x) s_sup[j] = g_sup[j];
    __syncthreads();

    int t = blockIdx.x * blockDim.x + threadIdx.x;
    if (t >= NT) return;
    int s = kb[3 * t];
    for (int j = 0; j < ns; j++) {
        int p = s_sup[j];
        if ((p & 0x1FFFF) == s) {
            int b = p >> 17;
            int i = atomicAdd(&g_cnt2, 1);
            if (i < MAX2) g_list2[i] = t * 4 + b;
        }
    }
}

// K5: step-1 full GRU cell per hop-2 triple; accumulate last0*p into hash2.
__global__ void k_hop2_proc(const int* __restrict__ kb, const float* __restrict__ rel_emb,
                            const float* __restrict__ W_step, const float* __restrict__ b_step,
                            const int* __restrict__ query,
                            const float* __restrict__ w_ih, const float* __restrict__ w_hh,
                            const float* __restrict__ b_ih, const float* __restrict__ b_hh,
                            const float* __restrict__ w_cls, const float* __restrict__ b_cls)
{
    __shared__ float s_cq[NB][ND];
    __shared__ float s_rf[ND], s_h[ND], s_red[ND];
    __shared__ int   s_slot;
    int d = threadIdx.x;

    #pragma unroll
    for (int b = 0; b < NB; b++) {
        int q = query[b];
        float acc = b_step[ND + d];                  // step 1
        #pragma unroll 8
        for (int i = 0; i < ND; i++)
            acc += rel_emb[q * ND + i] * W_step[ND * ND + i * ND + d];
        s_cq[b][d] = tanhf(acc);
    }
    __syncthreads();

    int n = min(g_cnt2, MAX2);
    for (int i = blockIdx.x; i < n; i += gridDim.x) {
        int code = g_list2[i];
        int t = code >> 2, b = code & 3;
        int s = kb[3 * t], e = kb[3 * t + 1], rid = kb[3 * t + 2];

        if (d == 0) s_slot = hfind1(b * NE + s);     // guaranteed found
        __syncthreads();
        int slot = s_slot;
        float ep = g_hep[slot];
        s_h[d]  = g_hhist[slot][d] / (ep + EPSV);    // hist = seg(obj_feat)/(obj_ep+eps)
        s_rf[d] = rel_emb[rid * ND + d];
        __syncthreads();

        float xr = b_ih[d], xz = b_ih[ND + d], xn = b_ih[2 * ND + d];
        float hr = b_hh[d], hz = b_hh[ND + d], hn = b_hh[2 * ND + d];
        const float* wir = w_ih + d * ND;
        const float* wiz = w_ih + (ND + d) * ND;
        const float* win = w_ih + (2 * ND + d) * ND;
        const float* whr = w_hh + d * ND;
        const float* whz = w_hh + (ND + d) * ND;
        const float* whn = w_hh + (2 * ND + d) * ND;
        #pragma unroll 4
        for (int k = 0; k < ND; k++) {
            float f = s_rf[k], hh = s_h[k];
            xr += f * wir[k]; xz += f * wiz[k]; xn += f * win[k];
            hr += hh * whr[k]; hz += hh * whz[k]; hn += hh * whn[k];
        }
        float r  = sigm(xr + hr);
        float z  = sigm(xz + hz);
        float nn = tanhf(xn + r * hn);
        float hd = s_h[d];
        float trans = (1.0f - z) * nn + z * hd;

        s_red[d] = trans * s_cq[b][d] * w_cls[d];
        __syncthreads();
        if (d == 0) {
            float logit = b_cls[0];
            for (int k = 0; k < ND; k++) logit += s_red[k];
            float p = sigm(logit);
            float last0 = fminf(ep, 1.0f);           // = obj_ep/zden
            int sl2 = hinsert2(b * NE + e);
            if (sl2 >= 0) atomicAdd(&g_h2ep[sl2], last0 * p);
        }
        __syncthreads();
    }
}

// K6: scatter hash2 -> out with final clamp  (last_e = min(obj_ep, 1))
__global__ void k_scatter(float* __restrict__ out)
{
    int i = blockIdx.x * blockDim.x + threadIdx.x;
    if (i < HSZ2) {
        int k = g_h2key[i];
        if (k >= 0) out[k] = fminf(g_h2ep[i], 1.0f);
    }
}

extern "C" void kernel_launch(void* const* d_in, const int* in_sizes, int n_in,
                              void* d_out, int out_size)
{
    const float* start   = (const float*)d_in[0];
    const float* rel_emb = (const float*)d_in[1];
    const float* W_step  = (const float*)d_in[2];
    const float* b_step  = (const float*)d_in[3];
    const float* w_ih    = (const float*)d_in[4];
    const float* w_hh    = (const float*)d_in[5];
    const float* b_ih    = (const float*)d_in[6];
    const float* b_hh    = (const float*)d_in[7];
    const float* w_cls   = (const float*)d_in[8];
    const float* b_cls   = (const float*)d_in[9];
    const int*   query   = (const int*)d_in[10];
    const int*   kb      = (const int*)d_in[11];
    float* out = (float*)d_out;

    k_init<<<(NB * NE / 4 + 255) / 256, 256>>>((const float4*)start, (float4*)out);
    k_hop1_collect<<<(NT + 255) / 256, 256>>>(kb);
    k_hop1_proc<<<64, ND>>>(kb, rel_emb, W_step, b_step, query,
                            w_ih, b_ih, b_hh, w_cls, b_cls);
    k_hop2_collect<<<(NT + 255) / 256, 256>>>(kb);
    k_hop2_proc<<<128, ND>>>(kb, rel_emb, W_step, b_step, query,
                             w_ih, w_hh, b_ih, b_hh, w_cls, b_cls);
    k_scatter<<<(HSZ2 + 255) / 256, 256>>>(out);
}